// round 16
// baseline (speedup 1.0000x reference)
#include <cuda_runtime.h>
#include <cuda_bf16.h>
#include <cstdint>

#define BATCH 64
#define SEQ   512
#define DIM   1024
#define TAGS  32
#define NSUB  32      // 16-step sub-chunks per batch

__device__ float g_x[BATCH * SEQ * TAGS];
__device__ float g_fvec[BATCH][NSUB][TAGS];
__device__ float g_bvec[BATCH][NSUB][TAGS];
__device__ float g_flog[BATCH][NSUB];
__device__ float g_blog[BATCH][NSUB];
__device__ float g_scorep[BATCH][4];
__device__ float g_llh[BATCH];
__device__ int   g_doneb[BATCH];
__device__ int   g_done;

// ---------------------------------------------------------------------------
// Kernel 1: emissions GEMM (proven 29.6us standalone design; adds PDL signal).
// ---------------------------------------------------------------------------
__device__ __forceinline__ void mma_bf16(float& d0, float& d1, float& d2, float& d3,
                                         uint32_t a0, uint32_t a1, uint32_t a2, uint32_t a3,
                                         uint32_t b0, uint32_t b1) {
    asm volatile(
        "mma.sync.aligned.m16n8k16.row.col.f32.bf16.bf16.f32 "
        "{%0,%1,%2,%3}, {%4,%5,%6,%7}, {%8,%9}, {%0,%1,%2,%3};\n"
        : "+f"(d0), "+f"(d1), "+f"(d2), "+f"(d3)
        : "r"(a0), "r"(a1), "r"(a2), "r"(a3), "r"(b0), "r"(b1));
}

__device__ __forceinline__ uint32_t pack_bf16(float lo, float hi) {
    __nv_bfloat162 h = __floats2bfloat162_rn(lo, hi);
    return *reinterpret_cast<uint32_t*>(&h);
}

#define ASTRIDE 68
#define WSTRIDE 40

__global__ __launch_bounds__(256)
void emissions_gemm_kernel(const float* __restrict__ feat,
                           const float* __restrict__ Wg,
                           const float* __restrict__ bias,
                           float* __restrict__ xout) {
    __shared__ uint32_t Asm[64 * ASTRIDE];
    __shared__ uint32_t Wp [64 * WSTRIDE];

    const int tid  = threadIdx.x;
    const int lane = tid & 31;
    const int w    = tid >> 5;
    const int m0   = blockIdx.x * 64;

    float4 areg[8];
    float  wlo[8], whi[8];

#pragma unroll
    for (int i = 0; i < 8; i++) {
        const int idx = tid + i * 256;
        const int row = idx >> 5, kq = idx & 31;
        areg[i] = *reinterpret_cast<const float4*>(
            feat + (size_t)(m0 + row) * DIM + 4 * kq);
    }
#pragma unroll
    for (int i = 0; i < 8; i++) {
        const int idx = tid + i * 256;
        const int kp = idx >> 5, n = idx & 31;
        wlo[i] = Wg[(size_t)(2 * kp) * TAGS + n];
        whi[i] = Wg[(size_t)(2 * kp + 1) * TAGS + n];
    }

    float acc[2][4];
#pragma unroll
    for (int f = 0; f < 2; f++)
#pragma unroll
        for (int j = 0; j < 4; j++) acc[f][j] = 0.f;

    const int rb = (w & 3) * 16;
    const int nb = (w >> 2) * 16;
    const int g  = lane >> 2;
    const int t  = lane & 3;

    for (int c = 0; c < 8; c++) {
#pragma unroll
        for (int i = 0; i < 8; i++) {
            const int idx = tid + i * 256;
            const int row = idx >> 5, kq = idx & 31;
            Asm[row * ASTRIDE + 2 * kq]     = pack_bf16(areg[i].x, areg[i].y);
            Asm[row * ASTRIDE + 2 * kq + 1] = pack_bf16(areg[i].z, areg[i].w);
        }
#pragma unroll
        for (int i = 0; i < 8; i++) {
            const int idx = tid + i * 256;
            const int kp = idx >> 5, n = idx & 31;
            Wp[kp * WSTRIDE + n] = pack_bf16(wlo[i], whi[i]);
        }
        __syncthreads();

        if (c < 7) {
            const int kc = (c + 1) * 128;
#pragma unroll
            for (int i = 0; i < 8; i++) {
                const int idx = tid + i * 256;
                const int row = idx >> 5, kq = idx & 31;
                areg[i] = *reinterpret_cast<const float4*>(
                    feat + (size_t)(m0 + row) * DIM + kc + 4 * kq);
            }
#pragma unroll
            for (int i = 0; i < 8; i++) {
                const int idx = tid + i * 256;
                const int kp = idx >> 5, n = idx & 31;
                wlo[i] = Wg[(size_t)(kc + 2 * kp) * TAGS + n];
                whi[i] = Wg[(size_t)(kc + 2 * kp + 1) * TAGS + n];
            }
        }

#pragma unroll
        for (int kf = 0; kf < 8; kf++) {
            const int kw = 8 * kf;
            const uint32_t a0 = Asm[(rb + g)     * ASTRIDE + kw + t];
            const uint32_t a1 = Asm[(rb + g + 8) * ASTRIDE + kw + t];
            const uint32_t a2 = Asm[(rb + g)     * ASTRIDE + kw + 4 + t];
            const uint32_t a3 = Asm[(rb + g + 8) * ASTRIDE + kw + 4 + t];
#pragma unroll
            for (int f = 0; f < 2; f++) {
                const uint32_t b0 = Wp[(kw + t)     * WSTRIDE + nb + 8 * f + g];
                const uint32_t b1 = Wp[(kw + 4 + t) * WSTRIDE + nb + 8 * f + g];
                mma_bf16(acc[f][0], acc[f][1], acc[f][2], acc[f][3],
                         a0, a1, a2, a3, b0, b1);
            }
        }
        __syncthreads();
    }

    const int c2 = 2 * t;
    const int row0 = m0 + rb + g;
#pragma unroll
    for (int f = 0; f < 2; f++) {
        const int col = nb + 8 * f + c2;
        const float bv0 = bias[col], bv1 = bias[col + 1];
        *reinterpret_cast<float2*>(xout + (size_t)row0 * TAGS + col) =
            make_float2(acc[f][0] + bv0, acc[f][1] + bv1);
        *reinterpret_cast<float2*>(xout + (size_t)(row0 + 8) * TAGS + col) =
            make_float2(acc[f][2] + bv0, acc[f][3] + bv1);
    }

    asm volatile("griddepcontrol.launch_dependents;");
}

// ---------------------------------------------------------------------------
// Kernel 2: parallel CRF chains. 256 blocks=(b,q), 512 threads, 1 block/SM
// (launch_bounds minBlocks=1 -> up to 128 regs, NO spills).
// ---------------------------------------------------------------------------
__device__ __forceinline__ int tag_at(const int* __restrict__ tg, int idx, bool is64) {
    return is64 ? __ldg(tg + 2 * idx) : __ldg(tg + idx);
}

__device__ __forceinline__ float dot32(const float* __restrict__ q,
                                       const float* __restrict__ Tc) {
    const float4 q0 = *reinterpret_cast<const float4*>(q + 0);
    const float4 q1 = *reinterpret_cast<const float4*>(q + 4);
    const float4 q2 = *reinterpret_cast<const float4*>(q + 8);
    const float4 q3 = *reinterpret_cast<const float4*>(q + 12);
    const float4 q4 = *reinterpret_cast<const float4*>(q + 16);
    const float4 q5 = *reinterpret_cast<const float4*>(q + 20);
    const float4 q6 = *reinterpret_cast<const float4*>(q + 24);
    const float4 q7 = *reinterpret_cast<const float4*>(q + 28);
    float s0 = q0.x * Tc[0],  s1 = q0.y * Tc[1];
    float s2 = q0.z * Tc[2],  s3 = q0.w * Tc[3];
    s0 = fmaf(q1.x, Tc[4],  s0); s1 = fmaf(q1.y, Tc[5],  s1);
    s2 = fmaf(q1.z, Tc[6],  s2); s3 = fmaf(q1.w, Tc[7],  s3);
    s0 = fmaf(q2.x, Tc[8],  s0); s1 = fmaf(q2.y, Tc[9],  s1);
    s2 = fmaf(q2.z, Tc[10], s2); s3 = fmaf(q2.w, Tc[11], s3);
    s0 = fmaf(q3.x, Tc[12], s0); s1 = fmaf(q3.y, Tc[13], s1);
    s2 = fmaf(q3.z, Tc[14], s2); s3 = fmaf(q3.w, Tc[15], s3);
    s0 = fmaf(q4.x, Tc[16], s0); s1 = fmaf(q4.y, Tc[17], s1);
    s2 = fmaf(q4.z, Tc[18], s2); s3 = fmaf(q4.w, Tc[19], s3);
    s0 = fmaf(q5.x, Tc[20], s0); s1 = fmaf(q5.y, Tc[21], s1);
    s2 = fmaf(q5.z, Tc[22], s2); s3 = fmaf(q5.w, Tc[23], s3);
    s0 = fmaf(q6.x, Tc[24], s0); s1 = fmaf(q6.y, Tc[25], s1);
    s2 = fmaf(q6.z, Tc[26], s2); s3 = fmaf(q6.w, Tc[27], s3);
    s0 = fmaf(q7.x, Tc[28], s0); s1 = fmaf(q7.y, Tc[29], s1);
    s2 = fmaf(q7.z, Tc[30], s2); s3 = fmaf(q7.w, Tc[31], s3);
    return (s0 + s1) + (s2 + s3);
}

__global__ __launch_bounds__(512, 1)
void crf_chain_kernel(const int* __restrict__ tags,
                      const float* __restrict__ start_t,
                      const float* __restrict__ end_t,
                      const float* __restrict__ trans,
                      float* __restrict__ out) {
    __shared__ __align__(16) float Esm[8][16][32];   // exp(x) for this quarter
    __shared__ float expT[32 * 33];
    __shared__ __align__(16) float psF[8][2][32];
    __shared__ __align__(16) float psB[8][2][32];
    __shared__ int s_len, s_win, s_win2;

    const unsigned F = 0xffffffffu;
    const int tid  = threadIdx.x;
    const int lane = tid & 31;
    const int w    = tid >> 5;          // 0..15
    const int wf   = w & 7;
    const int b = blockIdx.x >> 2;
    const int q = blockIdx.x & 3;
    const int base = b * SEQ;

    // ---------- setup that does NOT need g_x (overlaps GEMM via PDL) --------
    for (int idx = tid; idx < 1024; idx += 512) {
        const int i = idx >> 5, j = idx & 31;
        expT[i * 33 + j] = __expf(__ldg(trans + idx));
    }

    const int v1 = tags[2 * lane + 1];
    const int v2 = tags[2 * lane + 65];
    const bool okd = (v1 == 0 || v1 == -1) && (v2 == 0 || v2 == -1);
    const bool is64 = __all_sync(F, okd);

    if (w == 0) {
        int len = 0;
#pragma unroll
        for (int k = 0; k < 16; k++) {
            const int tv = tag_at(tags, base + k * 32 + lane, is64);
            len += __popc(__ballot_sync(F, tv != -1));
        }
        if (lane == 0) s_len = len;
    }

    // ---------- gate on GEMM completion, then load emissions ---------------
    asm volatile("griddepcontrol.wait;" ::: "memory");

    const int cc = 8 * q + wf;
    {
        const int half = w >> 3;
        const float* xg = g_x + (size_t)(base + 16 * cc + 8 * half) * TAGS + lane;
#pragma unroll
        for (int r = 0; r < 8; r++)
            Esm[wf][8 * half + r][lane] = __expf(__ldg(xg + r * 32));
    }
    __syncthreads();

    const int len = s_len;
    const int cl = (len - 1) >> 4;

    if (w < 8) {
        // ----- forward chain -----
        if (cc <= cl - 1) {
            float Tc[32];
#pragma unroll
            for (int i = 0; i < 32; i++) Tc[i] = expT[i * 33 + lane];

            float p, Cf = 0.f;
            int r0;
            if (cc == 0) { p = __expf(__ldg(start_t + lane)) * Esm[0][0][lane]; r0 = 1; }
            else         { p = 1.f;                                             r0 = 0; }
            psF[wf][0][lane] = p;
            int bp = 0;
            int r = r0;
            const int nst = 16 - r0;

#define FSTEP(RENORM)                                                          \
    {                                                                          \
        __syncwarp();                                                          \
        const float m_ = psF[wf][bp][0];                                       \
        const float s_ = dot32(&psF[wf][bp][0], Tc);                           \
        float pn = s_ * Esm[wf][r][lane];                                      \
        if (RENORM) {                                                          \
            float inv_;                                                        \
            asm("rcp.approx.f32 %0, %1;" : "=f"(inv_) : "f"(m_));              \
            pn *= inv_; Cf += __logf(m_);                                      \
        }                                                                      \
        p = pn; psF[wf][bp ^ 1][lane] = p; bp ^= 1; r++;                       \
    }
            const int n4 = nst >> 2;
            for (int k = 0; k < n4; k++) {
                FSTEP(0) FSTEP(0) FSTEP(0)
                if (k & 1) { FSTEP(1) } else { FSTEP(0) }
            }
            const int rem = nst & 3;
            for (int k = 0; k < rem; k++) { FSTEP(0) }
#undef FSTEP
            const float m = __shfl_sync(F, p, 0);
            float inv; asm("rcp.approx.f32 %0, %1;" : "=f"(inv) : "f"(m));
            p *= inv; Cf += __logf(m);
            g_fvec[b][cc][lane] = p;
            if (lane == 0) g_flog[b][cc] = Cf;
        }

        // ----- numerator partial (warp 0), rows [128q, 128q+128) -----
        if (w == 0) {
            float acc = 0.f;
#pragma unroll
            for (int r = 0; r < 4; r++) {
                const int t = 128 * q + r * 32 + lane;
                const int tg = tag_at(tags, base + t, is64);
                const bool valid = tg >= 0;
                int tgp = __shfl_up_sync(F, tg, 1);
                if (lane == 0) tgp = (t == 0) ? 0 : tag_at(tags, base + t - 1, is64);
                const int tgc = valid ? tg : 0;
                const int tgpc = tgp >= 0 ? tgp : 0;
                const float em = __ldg(g_x + (size_t)(base + t) * TAGS + tgc);
                const float tr = (t == 0) ? __ldg(start_t + tgc)
                                          : __ldg(trans + tgpc * 32 + tgc);
                float co = valid ? (tr + em) : 0.f;
                if (valid && t == len - 1) co += __ldg(end_t + tgc);
                acc += co;
            }
#pragma unroll
            for (int off = 16; off > 0; off >>= 1)
                acc += __shfl_xor_sync(F, acc, off);
            if (lane == 0) g_scorep[b][q] = acc;
        }
    } else {
        // ----- backward chain -----
        if (cc >= 1 && cc <= cl) {
            float Tr[32];
#pragma unroll
            for (int j = 0; j < 32; j++) Tr[j] = expT[lane * 33 + j];

            const int hi = (16 * cc + 15 < len - 1) ? 15 : (len - 1 - 16 * cc);
            const int nst = hi + 1;
            float wv = (cc == cl) ? __expf(__ldg(end_t + lane)) : 1.f;
            float Gb = 0.f;
            int tl = hi;
            psB[wf][0][lane] = wv * Esm[wf][tl][lane];
            int bp = 0;

#define BSTEP(RENORM)                                                          \
    {                                                                          \
        __syncwarp();                                                          \
        const float m_ = psB[wf][bp][0];                                       \
        float s_ = dot32(&psB[wf][bp][0], Tr);                                 \
        if (RENORM) {                                                          \
            float inv_;                                                        \
            asm("rcp.approx.f32 %0, %1;" : "=f"(inv_) : "f"(m_));              \
            s_ *= inv_; Gb += __logf(m_);                                      \
        }                                                                      \
        wv = s_;                                                               \
        tl--;                                                                  \
        const int il_ = tl < 0 ? 0 : tl;                                       \
        psB[wf][bp ^ 1][lane] = wv * Esm[wf][il_][lane];                       \
        bp ^= 1;                                                               \
    }
            const int n4 = nst >> 2;
            for (int k = 0; k < n4; k++) {
                BSTEP(0) BSTEP(0) BSTEP(0)
                if (k & 1) { BSTEP(1) } else { BSTEP(0) }
            }
            const int rem = nst & 3;
            for (int k = 0; k < rem; k++) { BSTEP(0) }
#undef BSTEP
            const float m = __shfl_sync(F, wv, 0);
            float inv; asm("rcp.approx.f32 %0, %1;" : "=f"(inv) : "f"(m));
            wv *= inv; Gb += __logf(m);
            g_bvec[b][cc][lane] = wv;
            if (lane == 0) g_blog[b][cc] = Gb;
        }
    }

    // ======================= tickets + combine ============================
    __syncthreads();
    if (tid == 0) {
        __threadfence();
        const int old = atomicAdd(&g_doneb[b], 1);
        s_win = (old == 3);
        s_win2 = 0;
    }
    __syncthreads();
    if (!s_win) return;

    if (w == 0) {
        __threadfence();
        const int clb = (len - 1) >> 4;
        float term = 0.f;
        if (lane >= 1 && lane <= clb) {
            float dotv = 0.f;
            const float* bv = g_bvec[b][lane];
            const float* fv = g_fvec[b][lane - 1];
#pragma unroll
            for (int i = 0; i < 32; i++) dotv += bv[i] * fv[i];
            term = g_blog[b][lane] + __logf(dotv);
            if (lane <= clb - 1) {
                float sumv = 0.f;
                const float* fc = g_fvec[b][lane];
#pragma unroll
                for (int i = 0; i < 32; i++) sumv += fc[i];
                term -= __logf(sumv);
            }
        }
#pragma unroll
        for (int off = 16; off > 0; off >>= 1)
            term += __shfl_xor_sync(F, term, off);
        const float logZ = g_flog[b][0] + term;

        if (lane == 0) {
            float score = 0.f;
#pragma unroll
            for (int q2 = 0; q2 < 4; q2++) score += g_scorep[b][q2];
            g_llh[b] = score - logZ;
        }
    }
    __syncthreads();
    if (tid == 0) {
        __threadfence();
        const int o2 = atomicAdd(&g_done, 1);
        s_win2 = (o2 == BATCH - 1);
    }
    __syncthreads();
    if (s_win2 && w == 0) {
        __threadfence();
        float v = g_llh[lane] + g_llh[lane + 32];
#pragma unroll
        for (int off = 16; off > 0; off >>= 1)
            v += __shfl_xor_sync(F, v, off);
        if (lane == 0) out[0] = -v * (1.0f / (float)BATCH);
        g_doneb[lane] = 0;
        g_doneb[lane + 32] = 0;
        if (lane == 0) g_done = 0;
    }
}

// ---------------------------------------------------------------------------
extern "C" void kernel_launch(void* const* d_in, const int* in_sizes, int n_in,
                              void* d_out, int out_size) {
    const float* feat    = (const float*)d_in[0];
    const int*   tags    = (const int*)  d_in[1];
    const float* W       = (const float*)d_in[2];
    const float* bias    = (const float*)d_in[3];
    const float* start_t = (const float*)d_in[4];
    const float* end_t   = (const float*)d_in[5];
    const float* trans   = (const float*)d_in[6];
    float* out = (float*)d_out;

    float* xg = nullptr;
    cudaGetSymbolAddress((void**)&xg, g_x);

    emissions_gemm_kernel<<<(BATCH * SEQ) / 64, 256>>>(feat, W, bias, xg);

    cudaLaunchConfig_t cfg = {};
    cfg.gridDim  = dim3(BATCH * 4, 1, 1);
    cfg.blockDim = dim3(512, 1, 1);
    cfg.dynamicSmemBytes = 0;
    cfg.stream = 0;
    cudaLaunchAttribute attrs[1];
    attrs[0].id = cudaLaunchAttributeProgrammaticStreamSerialization;
    attrs[0].val.programmaticStreamSerializationAllowed = 1;
    cfg.attrs = attrs;
    cfg.numAttrs = 1;
    cudaLaunchKernelEx(&cfg, crf_chain_kernel, tags, start_t, end_t, trans, out);
}

// round 17
// speedup vs baseline: 1.0501x; 1.0501x over previous
#include <cuda_runtime.h>
#include <cuda_bf16.h>
#include <cstdint>

#define BATCH 64
#define SEQ   512
#define DIM   1024
#define TAGS  32
#define NSUB  32      // 16-step sub-chunks per batch

#define C24   16.63553233343869f   // 24 * ln(2)
#define SCALE24 5.9604644775390625e-8f  // 2^-24

__device__ float g_x [BATCH * SEQ * TAGS];   // raw emissions (numerator)
__device__ float g_ex[BATCH * SEQ * TAGS];   // exp(emissions) (chains)
__device__ float g_expT[TAGS * TAGS];        // exp(trans)
__device__ float g_fvec[BATCH][NSUB][TAGS];
__device__ float g_bvec[BATCH][NSUB][TAGS];
__device__ float g_flog0[BATCH];
__device__ float g_blog[BATCH][NSUB];
__device__ float g_scorep[BATCH][4];
__device__ float g_llh[BATCH];
__device__ int   g_doneb[BATCH];
__device__ int   g_done;

// ---------------------------------------------------------------------------
// Kernel 1: emissions GEMM (proven design) + exp epilogue + expT + PDL signal.
// ---------------------------------------------------------------------------
__device__ __forceinline__ void mma_bf16(float& d0, float& d1, float& d2, float& d3,
                                         uint32_t a0, uint32_t a1, uint32_t a2, uint32_t a3,
                                         uint32_t b0, uint32_t b1) {
    asm volatile(
        "mma.sync.aligned.m16n8k16.row.col.f32.bf16.bf16.f32 "
        "{%0,%1,%2,%3}, {%4,%5,%6,%7}, {%8,%9}, {%0,%1,%2,%3};\n"
        : "+f"(d0), "+f"(d1), "+f"(d2), "+f"(d3)
        : "r"(a0), "r"(a1), "r"(a2), "r"(a3), "r"(b0), "r"(b1));
}

__device__ __forceinline__ uint32_t pack_bf16(float lo, float hi) {
    __nv_bfloat162 h = __floats2bfloat162_rn(lo, hi);
    return *reinterpret_cast<uint32_t*>(&h);
}

#define ASTRIDE 68
#define WSTRIDE 40

__global__ __launch_bounds__(256)
void emissions_gemm_kernel(const float* __restrict__ feat,
                           const float* __restrict__ Wg,
                           const float* __restrict__ bias,
                           const float* __restrict__ trans) {
    __shared__ uint32_t Asm[64 * ASTRIDE];
    __shared__ uint32_t Wp [64 * WSTRIDE];

    const int tid  = threadIdx.x;
    const int lane = tid & 31;
    const int w    = tid >> 5;
    const int m0   = blockIdx.x * 64;

    // block 0 also materializes exp(trans) for the chain kernel
    if (blockIdx.x == 0) {
        for (int idx = tid; idx < TAGS * TAGS; idx += 256)
            g_expT[idx] = __expf(__ldg(trans + idx));
    }

    float4 areg[8];
    float  wlo[8], whi[8];

#pragma unroll
    for (int i = 0; i < 8; i++) {
        const int idx = tid + i * 256;
        const int row = idx >> 5, kq = idx & 31;
        areg[i] = *reinterpret_cast<const float4*>(
            feat + (size_t)(m0 + row) * DIM + 4 * kq);
    }
#pragma unroll
    for (int i = 0; i < 8; i++) {
        const int idx = tid + i * 256;
        const int kp = idx >> 5, n = idx & 31;
        wlo[i] = Wg[(size_t)(2 * kp) * TAGS + n];
        whi[i] = Wg[(size_t)(2 * kp + 1) * TAGS + n];
    }

    float acc[2][4];
#pragma unroll
    for (int f = 0; f < 2; f++)
#pragma unroll
        for (int j = 0; j < 4; j++) acc[f][j] = 0.f;

    const int rb = (w & 3) * 16;
    const int nb = (w >> 2) * 16;
    const int g  = lane >> 2;
    const int t  = lane & 3;

    for (int c = 0; c < 8; c++) {
#pragma unroll
        for (int i = 0; i < 8; i++) {
            const int idx = tid + i * 256;
            const int row = idx >> 5, kq = idx & 31;
            Asm[row * ASTRIDE + 2 * kq]     = pack_bf16(areg[i].x, areg[i].y);
            Asm[row * ASTRIDE + 2 * kq + 1] = pack_bf16(areg[i].z, areg[i].w);
        }
#pragma unroll
        for (int i = 0; i < 8; i++) {
            const int idx = tid + i * 256;
            const int kp = idx >> 5, n = idx & 31;
            Wp[kp * WSTRIDE + n] = pack_bf16(wlo[i], whi[i]);
        }
        __syncthreads();

        if (c < 7) {
            const int kc = (c + 1) * 128;
#pragma unroll
            for (int i = 0; i < 8; i++) {
                const int idx = tid + i * 256;
                const int row = idx >> 5, kq = idx & 31;
                areg[i] = *reinterpret_cast<const float4*>(
                    feat + (size_t)(m0 + row) * DIM + kc + 4 * kq);
            }
#pragma unroll
            for (int i = 0; i < 8; i++) {
                const int idx = tid + i * 256;
                const int kp = idx >> 5, n = idx & 31;
                wlo[i] = Wg[(size_t)(kc + 2 * kp) * TAGS + n];
                whi[i] = Wg[(size_t)(kc + 2 * kp + 1) * TAGS + n];
            }
        }

#pragma unroll
        for (int kf = 0; kf < 8; kf++) {
            const int kw = 8 * kf;
            const uint32_t a0 = Asm[(rb + g)     * ASTRIDE + kw + t];
            const uint32_t a1 = Asm[(rb + g + 8) * ASTRIDE + kw + t];
            const uint32_t a2 = Asm[(rb + g)     * ASTRIDE + kw + 4 + t];
            const uint32_t a3 = Asm[(rb + g + 8) * ASTRIDE + kw + 4 + t];
#pragma unroll
            for (int f = 0; f < 2; f++) {
                const uint32_t b0 = Wp[(kw + t)     * WSTRIDE + nb + 8 * f + g];
                const uint32_t b1 = Wp[(kw + 4 + t) * WSTRIDE + nb + 8 * f + g];
                mma_bf16(acc[f][0], acc[f][1], acc[f][2], acc[f][3],
                         a0, a1, a2, a3, b0, b1);
            }
        }
        __syncthreads();
    }

    const int c2 = 2 * t;
    const int row0 = m0 + rb + g;
#pragma unroll
    for (int f = 0; f < 2; f++) {
        const int col = nb + 8 * f + c2;
        const float bv0 = bias[col], bv1 = bias[col + 1];
        const float x00 = acc[f][0] + bv0, x01 = acc[f][1] + bv1;
        const float x10 = acc[f][2] + bv0, x11 = acc[f][3] + bv1;
        *reinterpret_cast<float2*>(g_x + (size_t)row0 * TAGS + col) =
            make_float2(x00, x01);
        *reinterpret_cast<float2*>(g_x + (size_t)(row0 + 8) * TAGS + col) =
            make_float2(x10, x11);
        *reinterpret_cast<float2*>(g_ex + (size_t)row0 * TAGS + col) =
            make_float2(__expf(x00), __expf(x01));
        *reinterpret_cast<float2*>(g_ex + (size_t)(row0 + 8) * TAGS + col) =
            make_float2(__expf(x10), __expf(x11));
    }

    asm volatile("griddepcontrol.launch_dependents;");
}

// ---------------------------------------------------------------------------
// Kernel 2: parallel CRF chains. 256 blocks=(b,q), 512 threads.
// No MUFU in the hot loops: emissions pre-exp'd (g_ex), exp(trans) pre-built
// (g_expT), renorm = fixed 2^-24 per 4-step group (compensation n4*24ln2).
// ---------------------------------------------------------------------------
__device__ __forceinline__ int tag_at(const int* __restrict__ tg, int idx, bool is64) {
    return is64 ? __ldg(tg + 2 * idx) : __ldg(tg + idx);
}

__device__ __forceinline__ float dot32(const float* __restrict__ q,
                                       const float* __restrict__ Tc) {
    const float4 q0 = *reinterpret_cast<const float4*>(q + 0);
    const float4 q1 = *reinterpret_cast<const float4*>(q + 4);
    const float4 q2 = *reinterpret_cast<const float4*>(q + 8);
    const float4 q3 = *reinterpret_cast<const float4*>(q + 12);
    const float4 q4 = *reinterpret_cast<const float4*>(q + 16);
    const float4 q5 = *reinterpret_cast<const float4*>(q + 20);
    const float4 q6 = *reinterpret_cast<const float4*>(q + 24);
    const float4 q7 = *reinterpret_cast<const float4*>(q + 28);
    float s0 = q0.x * Tc[0],  s1 = q0.y * Tc[1];
    float s2 = q0.z * Tc[2],  s3 = q0.w * Tc[3];
    s0 = fmaf(q1.x, Tc[4],  s0); s1 = fmaf(q1.y, Tc[5],  s1);
    s2 = fmaf(q1.z, Tc[6],  s2); s3 = fmaf(q1.w, Tc[7],  s3);
    s0 = fmaf(q2.x, Tc[8],  s0); s1 = fmaf(q2.y, Tc[9],  s1);
    s2 = fmaf(q2.z, Tc[10], s2); s3 = fmaf(q2.w, Tc[11], s3);
    s0 = fmaf(q3.x, Tc[12], s0); s1 = fmaf(q3.y, Tc[13], s1);
    s2 = fmaf(q3.z, Tc[14], s2); s3 = fmaf(q3.w, Tc[15], s3);
    s0 = fmaf(q4.x, Tc[16], s0); s1 = fmaf(q4.y, Tc[17], s1);
    s2 = fmaf(q4.z, Tc[18], s2); s3 = fmaf(q4.w, Tc[19], s3);
    s0 = fmaf(q5.x, Tc[20], s0); s1 = fmaf(q5.y, Tc[21], s1);
    s2 = fmaf(q5.z, Tc[22], s2); s3 = fmaf(q5.w, Tc[23], s3);
    s0 = fmaf(q6.x, Tc[24], s0); s1 = fmaf(q6.y, Tc[25], s1);
    s2 = fmaf(q6.z, Tc[26], s2); s3 = fmaf(q6.w, Tc[27], s3);
    s0 = fmaf(q7.x, Tc[28], s0); s1 = fmaf(q7.y, Tc[29], s1);
    s2 = fmaf(q7.z, Tc[30], s2); s3 = fmaf(q7.w, Tc[31], s3);
    return (s0 + s1) + (s2 + s3);
}

__global__ __launch_bounds__(512)
void crf_chain_kernel(const int* __restrict__ tags,
                      const float* __restrict__ start_t,
                      const float* __restrict__ end_t,
                      const float* __restrict__ trans,
                      float* __restrict__ out) {
    __shared__ __align__(16) float Esm[8][16][32];   // exp(x) for this quarter
    __shared__ float expT[32 * 33];
    __shared__ __align__(16) float psF[8][2][32];
    __shared__ __align__(16) float psB[8][2][32];
    __shared__ int s_len, s_win, s_win2;

    const unsigned F = 0xffffffffu;
    const int tid  = threadIdx.x;
    const int lane = tid & 31;
    const int w    = tid >> 5;          // 0..15
    const int wf   = w & 7;
    const int b = blockIdx.x >> 2;
    const int q = blockIdx.x & 3;
    const int base = b * SEQ;

    // ---------- setup that does NOT need GEMM output (overlaps via PDL) -----
    const int v1 = tags[2 * lane + 1];
    const int v2 = tags[2 * lane + 65];
    const bool okd = (v1 == 0 || v1 == -1) && (v2 == 0 || v2 == -1);
    const bool is64 = __all_sync(F, okd);

    if (w == 0) {
        int len = 0;
#pragma unroll
        for (int k = 0; k < 16; k++) {
            const int tv = tag_at(tags, base + k * 32 + lane, is64);
            len += __popc(__ballot_sync(F, tv != -1));
        }
        if (lane == 0) s_len = len;
    }

    // ---------- gate on GEMM, then load exp(trans) + emissions -------------
    asm volatile("griddepcontrol.wait;" ::: "memory");

    for (int idx = tid; idx < 1024; idx += 512) {
        const int i = idx >> 5, j = idx & 31;
        expT[i * 33 + j] = __ldg(g_expT + idx);
    }

    const int cc = 8 * q + wf;
    {
        const int half = w >> 3;
        const float* xg = g_ex + (size_t)(base + 16 * cc + 8 * half) * TAGS + lane;
#pragma unroll
        for (int r = 0; r < 8; r++)
            Esm[wf][8 * half + r][lane] = __ldg(xg + r * 32);
    }
    __syncthreads();

    const int len = s_len;
    const int cl = (len - 1) >> 4;

    if (w < 8) {
        // ----- forward chain for sub-chunk cc -----
        if (cc <= cl - 1) {
            float Tc[32];
#pragma unroll
            for (int i = 0; i < 32; i++) Tc[i] = expT[i * 33 + lane];

            float p;
            int r0;
            if (cc == 0) { p = __expf(__ldg(start_t + lane)) * Esm[0][0][lane]; r0 = 1; }
            else         { p = 1.f;                                             r0 = 0; }
            psF[wf][0][lane] = p;
            int bp = 0;
            int r = r0;
            const int nst = 16 - r0;

#define FSTEP(S)                                                               \
    {                                                                          \
        __syncwarp();                                                          \
        const float s_ = dot32(&psF[wf][bp][0], Tc);                           \
        p = s_ * Esm[wf][r][lane] * (S);                                       \
        psF[wf][bp ^ 1][lane] = p; bp ^= 1; r++;                               \
    }
            const int n4 = nst >> 2;
            for (int k = 0; k < n4; k++) {
                FSTEP(1.0f) FSTEP(1.0f) FSTEP(1.0f) FSTEP(SCALE24)
            }
            const int rem = nst & 3;
            for (int k = 0; k < rem; k++) { FSTEP(1.0f) }
#undef FSTEP
            g_fvec[b][cc][lane] = p;
            if (cc == 0 && lane == 0) g_flog0[b] = (float)n4 * C24;
        }

        // ----- numerator partial (warp 0), rows [128q, 128q+128) -----
        if (w == 0) {
            float acc = 0.f;
#pragma unroll
            for (int r = 0; r < 4; r++) {
                const int t = 128 * q + r * 32 + lane;
                const int tg = tag_at(tags, base + t, is64);
                const bool valid = tg >= 0;
                int tgp = __shfl_up_sync(F, tg, 1);
                if (lane == 0) tgp = (t == 0) ? 0 : tag_at(tags, base + t - 1, is64);
                const int tgc = valid ? tg : 0;
                const int tgpc = tgp >= 0 ? tgp : 0;
                const float em = __ldg(g_x + (size_t)(base + t) * TAGS + tgc);
                const float tr = (t == 0) ? __ldg(start_t + tgc)
                                          : __ldg(trans + tgpc * 32 + tgc);
                float co = valid ? (tr + em) : 0.f;
                if (valid && t == len - 1) co += __ldg(end_t + tgc);
                acc += co;
            }
#pragma unroll
            for (int off = 16; off > 0; off >>= 1)
                acc += __shfl_xor_sync(F, acc, off);
            if (lane == 0) g_scorep[b][q] = acc;
        }
    } else {
        // ----- backward chain for sub-chunk cc -----
        if (cc >= 1 && cc <= cl) {
            float Tr[32];
#pragma unroll
            for (int j = 0; j < 32; j++) Tr[j] = expT[lane * 33 + j];

            const int hi = (16 * cc + 15 < len - 1) ? 15 : (len - 1 - 16 * cc);
            const int nst = hi + 1;
            float wv = (cc == cl) ? __expf(__ldg(end_t + lane)) : 1.f;
            int tl = hi;
            psB[wf][0][lane] = wv * Esm[wf][tl][lane];
            int bp = 0;

#define BSTEP(S)                                                               \
    {                                                                          \
        __syncwarp();                                                          \
        wv = dot32(&psB[wf][bp][0], Tr) * (S);                                 \
        tl--;                                                                  \
        const int il_ = tl < 0 ? 0 : tl;                                       \
        psB[wf][bp ^ 1][lane] = wv * Esm[wf][il_][lane];                       \
        bp ^= 1;                                                               \
    }
            const int n4 = nst >> 2;
            for (int k = 0; k < n4; k++) {
                BSTEP(1.0f) BSTEP(1.0f) BSTEP(1.0f) BSTEP(SCALE24)
            }
            const int rem = nst & 3;
            for (int k = 0; k < rem; k++) { BSTEP(1.0f) }
#undef BSTEP
            g_bvec[b][cc][lane] = wv;
            if (lane == 0) g_blog[b][cc] = (float)n4 * C24;
        }
    }

    // ======================= tickets + combine ============================
    __syncthreads();
    if (tid == 0) {
        __threadfence();
        const int old = atomicAdd(&g_doneb[b], 1);
        s_win = (old == 3);
        s_win2 = 0;
    }
    __syncthreads();
    if (!s_win) return;

    if (w == 0) {
        __threadfence();
        const int clb = (len - 1) >> 4;
        float term = 0.f;
        if (lane >= 1 && lane <= clb) {
            float dotv = 0.f;
            const float* bv = g_bvec[b][lane];
            const float* fv = g_fvec[b][lane - 1];
#pragma unroll
            for (int i = 0; i < 32; i++) dotv += bv[i] * fv[i];
            term = g_blog[b][lane] + __logf(dotv);
            if (lane <= clb - 1) {
                float sumv = 0.f;
                const float* fc = g_fvec[b][lane];
#pragma unroll
                for (int i = 0; i < 32; i++) sumv += fc[i];
                term -= __logf(sumv);
            }
        }
#pragma unroll
        for (int off = 16; off > 0; off >>= 1)
            term += __shfl_xor_sync(F, term, off);
        const float logZ = g_flog0[b] + term;

        if (lane == 0) {
            float score = 0.f;
#pragma unroll
            for (int q2 = 0; q2 < 4; q2++) score += g_scorep[b][q2];
            g_llh[b] = score - logZ;
        }
    }
    __syncthreads();
    if (tid == 0) {
        __threadfence();
        const int o2 = atomicAdd(&g_done, 1);
        s_win2 = (o2 == BATCH - 1);
    }
    __syncthreads();
    if (s_win2 && w == 0) {
        __threadfence();
        float v = g_llh[lane] + g_llh[lane + 32];
#pragma unroll
        for (int off = 16; off > 0; off >>= 1)
            v += __shfl_xor_sync(F, v, off);
        if (lane == 0) out[0] = -v * (1.0f / (float)BATCH);
        g_doneb[lane] = 0;
        g_doneb[lane + 32] = 0;
        if (lane == 0) g_done = 0;
    }
}

// ---------------------------------------------------------------------------
extern "C" void kernel_launch(void* const* d_in, const int* in_sizes, int n_in,
                              void* d_out, int out_size) {
    const float* feat    = (const float*)d_in[0];
    const int*   tags    = (const int*)  d_in[1];
    const float* W       = (const float*)d_in[2];
    const float* bias    = (const float*)d_in[3];
    const float* start_t = (const float*)d_in[4];
    const float* end_t   = (const float*)d_in[5];
    const float* trans   = (const float*)d_in[6];
    float* out = (float*)d_out;

    emissions_gemm_kernel<<<(BATCH * SEQ) / 64, 256>>>(feat, W, bias, trans);

    cudaLaunchConfig_t cfg = {};
    cfg.gridDim  = dim3(BATCH * 4, 1, 1);
    cfg.blockDim = dim3(512, 1, 1);
    cfg.dynamicSmemBytes = 0;
    cfg.stream = 0;
    cudaLaunchAttribute attrs[1];
    attrs[0].id = cudaLaunchAttributeProgrammaticStreamSerialization;
    attrs[0].val.programmaticStreamSerializationAllowed = 1;
    cfg.attrs = attrs;
    cfg.numAttrs = 1;
    cudaLaunchKernelEx(&cfg, crf_chain_kernel, tags, start_t, end_t, trans, out);
}